// round 2
// baseline (speedup 1.0000x reference)
#include <cuda_runtime.h>
#include <math.h>

#define Dd   512
#define Hh   1024
#define Bb   4
#define Ss   4096
#define Cc   64
#define NCH  64           // S / CHUNK
#define Mm   256          // B * CHUNK rows per chunk
#define SCALEC (2.0f/131072.0f)   // 2 / (B*C*D)

// ---------------- persistent device scratch (no allocations allowed) --------
__device__ float g_k[NCH*Mm*Dd];     // chunked [n, B*C, D]
__device__ float g_v[NCH*Mm*Dd];
__device__ float g_q[NCH*Mm*Dd];
__device__ float g_y[NCH*Mm*Dd];
__device__ float g_W1e[Hh*Dd];       // Wm1 + d1
__device__ float g_W2e[Dd*Hh];       // Wm2 + d2
__device__ float g_d1[Hh*Dd];
__device__ float g_d2[Dd*Hh];
__device__ float g_m1[Hh*Dd];
__device__ float g_m2[Dd*Hh];
__device__ float g_pre1[Mm*Hh];
__device__ float g_a1[Mm*Hh];
__device__ float g_db2[Mm*Dd];
__device__ float g_db1[Mm*Hh];
__device__ float g_hbuf[Mm*Hh];
__device__ float g_gates[3*NCH];     // decay[64], lr[64], eta[64]

__device__ __forceinline__ float sigmoidf_(float x){ return 1.0f/(1.0f + expf(-x)); }
__device__ __forceinline__ float siluf_(float x){ return x * sigmoidf_(x); }
__device__ __forceinline__ float dsiluf_(float x){ float s = sigmoidf_(x); return s*(1.0f + x*(1.0f - s)); }
__device__ __forceinline__ float clip1f_(float x){ return fminf(1.0f, fmaxf(-1.0f, x)); }

// ---------------- generic 64x64x16 SGEMM tile core ---------------------------
// LAYOUT 0 (NT): C[m,n] = sum_k A[m,k] * B[n,k]
// LAYOUT 1 (NN): C[m,n] = sum_k A[m,k] * B[k,n]
// LAYOUT 2 (TN): C[m,n] = sum_k A[k,m] * B[k,n]
// blockDim = (16,16); each thread computes a 4x4 micro-tile.
template<int LAYOUT>
__device__ __forceinline__ void gemm_block(
    const float* __restrict__ A, const float* __restrict__ B,
    int K, int lda, int ldb, int m0, int n0, float acc[4][4])
{
    __shared__ float As[16][68];
    __shared__ float Bs[16][68];
    const int tid = threadIdx.y * 16 + threadIdx.x;

    for (int k0 = 0; k0 < K; k0 += 16) {
        // ---- load A tile into As[k][m]
        if (LAYOUT == 0 || LAYOUT == 1) {           // A[m,k] row-major
            int row = tid >> 2;
            int kq  = (tid & 3) * 4;
            float4 av = *(const float4*)&A[(size_t)(m0 + row) * lda + k0 + kq];
            As[kq+0][row] = av.x; As[kq+1][row] = av.y;
            As[kq+2][row] = av.z; As[kq+3][row] = av.w;
        } else {                                    // A[k,m] row-major
            int kr = tid >> 4;
            int mq = (tid & 15) * 4;
            float4 av = *(const float4*)&A[(size_t)(k0 + kr) * lda + m0 + mq];
            *(float4*)&As[kr][mq] = av;
        }
        // ---- load B tile into Bs[k][n]
        if (LAYOUT == 0) {                          // B[n,k] row-major
            int row = tid >> 2;
            int kq  = (tid & 3) * 4;
            float4 bv = *(const float4*)&B[(size_t)(n0 + row) * ldb + k0 + kq];
            Bs[kq+0][row] = bv.x; Bs[kq+1][row] = bv.y;
            Bs[kq+2][row] = bv.z; Bs[kq+3][row] = bv.w;
        } else {                                    // B[k,n] row-major
            int kr = tid >> 4;
            int nq = (tid & 15) * 4;
            float4 bv = *(const float4*)&B[(size_t)(k0 + kr) * ldb + n0 + nq];
            *(float4*)&Bs[kr][nq] = bv;
        }
        __syncthreads();
        #pragma unroll
        for (int kk = 0; kk < 16; kk++) {
            float4 a4 = *(const float4*)&As[kk][threadIdx.y * 4];
            float4 b4 = *(const float4*)&Bs[kk][threadIdx.x * 4];
            float av[4] = {a4.x, a4.y, a4.z, a4.w};
            float bv[4] = {b4.x, b4.y, b4.z, b4.w};
            #pragma unroll
            for (int i = 0; i < 4; i++)
                #pragma unroll
                for (int j = 0; j < 4; j++)
                    acc[i][j] += av[i] * bv[j];
        }
        __syncthreads();
    }
}

// ---------------- init: reset fast-weight state every launch -----------------
__global__ void init_kernel(const float* __restrict__ Wm1, const float* __restrict__ Wm2)
{
    int i = blockIdx.x * 256 + threadIdx.x;
    if (i < Hh * Dd) {
        g_d1[i] = 0.0f; g_m1[i] = 0.0f; g_W1e[i] = Wm1[i];
        g_d2[i] = 0.0f; g_m2[i] = 0.0f; g_W2e[i] = Wm2[i];
    }
}

// ---------------- projections: k/q/v = x @ W^T, written chunked --------------
__global__ __launch_bounds__(256)
void proj_kernel(const float* __restrict__ x,
                 const float* __restrict__ Wk,
                 const float* __restrict__ Wq,
                 const float* __restrict__ Wv)
{
    const float* B = (blockIdx.z == 0) ? Wk : ((blockIdx.z == 1) ? Wq : Wv);
    float* dst     = (blockIdx.z == 0) ? g_k : ((blockIdx.z == 1) ? g_q : g_v);
    float acc[4][4] = {};
    int m0 = blockIdx.y * 64, n0 = blockIdx.x * 64;
    gemm_block<0>(x, B, Dd, Dd, Dd, m0, n0, acc);
    int mbase = m0 + threadIdx.y * 4;
    int nbase = n0 + threadIdx.x * 4;
    #pragma unroll
    for (int i = 0; i < 4; i++) {
        int m = mbase + i;
        int b = m >> 12, s = m & 4095;
        int tt = s >> 6, c = s & 63;
        int row = (tt * Bb + b) * Cc + c;          // chunked row index
        #pragma unroll
        for (int j = 0; j < 4; j++)
            dst[(size_t)row * Dd + nbase + j] = acc[i][j];
    }
}

// ---------------- per-chunk scalar gates -------------------------------------
__global__ void gates_kernel(const float* __restrict__ x,
                             const float* __restrict__ gdw, const float* __restrict__ gdb,
                             const float* __restrict__ glw, const float* __restrict__ glb,
                             const float* __restrict__ gmw, const float* __restrict__ gmb)
{
    int t = blockIdx.x;
    int tid = threadIdx.x;                          // 256 threads, one per (b,c)
    __shared__ float ws[3][Dd];
    for (int j = tid; j < Dd; j += 256) { ws[0][j] = gdw[j]; ws[1][j] = glw[j]; ws[2][j] = gmw[j]; }
    __syncthreads();
    int b = tid >> 6, c = tid & 63;
    const float* xr = x + ((size_t)b * Ss + t * Cc + c) * Dd;
    float s0 = 0.f, s1 = 0.f, s2 = 0.f;
    for (int j = 0; j < Dd; j++) {
        float xv = xr[j];
        s0 += xv * ws[0][j]; s1 += xv * ws[1][j]; s2 += xv * ws[2][j];
    }
    s0 = sigmoidf_(s0 + gdb[0]); s1 = sigmoidf_(s1 + glb[0]); s2 = sigmoidf_(s2 + gmb[0]);
    __shared__ float red[3][256];
    red[0][tid] = s0; red[1][tid] = s1; red[2][tid] = s2;
    __syncthreads();
    for (int o = 128; o > 0; o >>= 1) {
        if (tid < o) {
            red[0][tid] += red[0][tid+o];
            red[1][tid] += red[1][tid+o];
            red[2][tid] += red[2][tid+o];
        }
        __syncthreads();
    }
    if (tid == 0) {
        g_gates[t]          = red[0][0] * (1.0f/256.0f);
        g_gates[NCH + t]    = red[1][0] * (1.0f/256.0f);
        g_gates[2*NCH + t]  = red[2][0] * (1.0f/256.0f);
    }
}

// ---------------- rowwise L2 normalize for k and q ---------------------------
__global__ void norm_kernel()
{
    float* base = blockIdx.y ? g_q : g_k;
    float* row = base + (size_t)blockIdx.x * Dd;
    int tid = threadIdx.x;                          // 128 threads x float4 = 512
    float4 v = reinterpret_cast<float4*>(row)[tid];
    float s = v.x*v.x + v.y*v.y + v.z*v.z + v.w*v.w;
    #pragma unroll
    for (int o = 16; o > 0; o >>= 1) s += __shfl_xor_sync(0xffffffffu, s, o);
    __shared__ float wsum[4];
    if ((tid & 31) == 0) wsum[tid >> 5] = s;
    __syncthreads();
    float tot = wsum[0] + wsum[1] + wsum[2] + wsum[3];
    float inv = 1.0f / (sqrtf(tot) + 1e-8f);
    v.x *= inv; v.y *= inv; v.z *= inv; v.w *= inv;
    reinterpret_cast<float4*>(row)[tid] = v;
}

// ---------------- chunk-loop GEMM stages -------------------------------------
// EPI 0: pre1 = kt @ W1e^T         -> g_pre1, g_a1=silu           [256,1024]
// EPI 1: pred = a1 @ W2e^T         -> g_db2 = clip(pred-v)*scale  [256, 512]
// EPI 2: db1 = (db2 @ W2e)*silu'   -> g_db1                       [256,1024]
// EPI 5: h = silu(qt @ W1e^T)      -> g_hbuf                      [256,1024]
// EPI 6: y = h @ W2e^T             -> g_y chunk slice             [256, 512]
template<int LAYOUT, int EPI>
__global__ __launch_bounds__(256)
void step_gemm(int t)
{
    const float* A; const float* B;
    int K, lda, ldb;
    if      (EPI == 0) { A = g_k + (size_t)t*Mm*Dd; B = g_W1e; K = Dd; lda = Dd; ldb = Dd; }
    else if (EPI == 1) { A = g_a1;                  B = g_W2e; K = Hh; lda = Hh; ldb = Hh; }
    else if (EPI == 2) { A = g_db2;                 B = g_W2e; K = Dd; lda = Dd; ldb = Hh; }
    else if (EPI == 5) { A = g_q + (size_t)t*Mm*Dd; B = g_W1e; K = Dd; lda = Dd; ldb = Dd; }
    else               { A = g_hbuf;                B = g_W2e; K = Hh; lda = Hh; ldb = Hh; }

    float acc[4][4] = {};
    int m0 = blockIdx.y * 64, n0 = blockIdx.x * 64;
    gemm_block<LAYOUT>(A, B, K, lda, ldb, m0, n0, acc);

    int mbase = m0 + threadIdx.y * 4;
    int nbase = n0 + threadIdx.x * 4;

    if (EPI == 0) {
        #pragma unroll
        for (int i = 0; i < 4; i++)
            #pragma unroll
            for (int j = 0; j < 4; j++) {
                int m = mbase + i, n = nbase + j;
                float p = acc[i][j];
                g_pre1[m*Hh + n] = p;
                g_a1[m*Hh + n]   = siluf_(p);
            }
    } else if (EPI == 1) {
        const float* v = g_v + (size_t)t*Mm*Dd;
        #pragma unroll
        for (int i = 0; i < 4; i++)
            #pragma unroll
            for (int j = 0; j < 4; j++) {
                int m = mbase + i, n = nbase + j;
                float e = clip1f_(acc[i][j] - v[m*Dd + n]);
                g_db2[m*Dd + n] = e * SCALEC;
            }
    } else if (EPI == 2) {
        #pragma unroll
        for (int i = 0; i < 4; i++)
            #pragma unroll
            for (int j = 0; j < 4; j++) {
                int m = mbase + i, n = nbase + j;
                g_db1[m*Hh + n] = acc[i][j] * dsiluf_(g_pre1[m*Hh + n]);
            }
    } else if (EPI == 5) {
        #pragma unroll
        for (int i = 0; i < 4; i++)
            #pragma unroll
            for (int j = 0; j < 4; j++) {
                int m = mbase + i, n = nbase + j;
                g_hbuf[m*Hh + n] = siluf_(acc[i][j]);
            }
    } else {
        float* y = g_y + (size_t)t*Mm*Dd;
        #pragma unroll
        for (int i = 0; i < 4; i++)
            #pragma unroll
            for (int j = 0; j < 4; j++) {
                int m = mbase + i, n = nbase + j;
                y[m*Dd + n] = acc[i][j];
            }
    }
}

// ---------------- merged weight-update kernel (g1->W1e and g2->W2e) ----------
// z==0: g1 = db1^T @ kt  [H,D]  (grid x over D/64=8?? no: m over H, n over D)
//       launched as grid (8,16,2): z0 uses m0 = by*64 (H), n0 = bx*64 (D)
// z==1: g2 = db2^T @ a1  [D,H]: m0 = bx*64 (D, 8 blocks), n0 = by*64 (H, 16 blocks)
__global__ __launch_bounds__(256)
void update_gemm(const float* __restrict__ Wm1, const float* __restrict__ Wm2, int t)
{
    float dec = g_gates[t], lr = g_gates[NCH + t], eta = g_gates[2*NCH + t];
    float acc[4][4] = {};

    if (blockIdx.z == 0) {
        // g1[m over H, n over D] = sum_r db1[r,m] * kt[r,n]
        int m0 = blockIdx.y * 64, n0 = blockIdx.x * 64;
        gemm_block<2>(g_db1, g_k + (size_t)t*Mm*Dd, Mm, Hh, Dd, m0, n0, acc);
        int mbase = m0 + threadIdx.y * 4;
        int nbase = n0 + threadIdx.x * 4;
        #pragma unroll
        for (int i = 0; i < 4; i++)
            #pragma unroll
            for (int j = 0; j < 4; j++) {
                int idx = (mbase + i)*Dd + nbase + j;
                float g = clip1f_(acc[i][j]);
                float mm = eta * g_m1[idx] - lr * g;
                g_m1[idx] = mm;
                float dd = (1.0f - dec) * g_d1[idx] + mm;
                g_d1[idx] = dd;
                g_W1e[idx] = Wm1[idx] + dd;
            }
    } else {
        // g2[m over D, n over H] = sum_r db2[r,m] * a1[r,n]
        int m0 = blockIdx.x * 64, n0 = blockIdx.y * 64;
        gemm_block<2>(g_db2, g_a1, Mm, Dd, Hh, m0, n0, acc);
        int mbase = m0 + threadIdx.y * 4;
        int nbase = n0 + threadIdx.x * 4;
        #pragma unroll
        for (int i = 0; i < 4; i++)
            #pragma unroll
            for (int j = 0; j < 4; j++) {
                int idx = (mbase + i)*Hh + nbase + j;
                float g = clip1f_(acc[i][j]);
                float mm = eta * g_m2[idx] - lr * g;
                g_m2[idx] = mm;
                float dd = (1.0f - dec) * g_d2[idx] + mm;
                g_d2[idx] = dd;
                g_W2e[idx] = Wm2[idx] + dd;
            }
    }
}

// ---------------- final: out = y @ Wout^T (undo chunk permutation) -----------
__global__ __launch_bounds__(256)
void final_kernel(const float* __restrict__ Wout, float* __restrict__ out)
{
    float acc[4][4] = {};
    int m0 = blockIdx.y * 64, n0 = blockIdx.x * 64;
    gemm_block<0>(g_y, Wout, Dd, Dd, Dd, m0, n0, acc);
    int mbase = m0 + threadIdx.y * 4;
    int nbase = n0 + threadIdx.x * 4;
    #pragma unroll
    for (int i = 0; i < 4; i++) {
        int m = mbase + i;
        int tt = m >> 8, b = (m >> 6) & 3, c = m & 63;
        size_t orow = (size_t)b * Ss + tt * Cc + c;
        #pragma unroll
        for (int j = 0; j < 4; j++)
            out[orow * Dd + nbase + j] = acc[i][j];
    }
}

// ---------------- launch ------------------------------------------------------
extern "C" void kernel_launch(void* const* d_in, const int* in_sizes, int n_in,
                              void* d_out, int out_size)
{
    const float* x    = (const float*)d_in[0];
    const float* Wk   = (const float*)d_in[1];
    const float* Wv   = (const float*)d_in[2];
    const float* Wq   = (const float*)d_in[3];
    const float* Wout = (const float*)d_in[4];
    const float* Wm1  = (const float*)d_in[5];
    const float* Wm2  = (const float*)d_in[6];
    const float* gd_w = (const float*)d_in[7];
    const float* gd_b = (const float*)d_in[8];
    const float* gl_w = (const float*)d_in[9];
    const float* gl_b = (const float*)d_in[10];
    const float* gm_w = (const float*)d_in[11];
    const float* gm_b = (const float*)d_in[12];
    float* out = (float*)d_out;

    dim3 thr(16, 16);

    init_kernel<<<(Hh*Dd + 255)/256, 256>>>(Wm1, Wm2);
    proj_kernel<<<dim3(Dd/64, (Bb*Ss)/64, 3), thr>>>(x, Wk, Wq, Wv);
    gates_kernel<<<NCH, 256>>>(x, gd_w, gd_b, gl_w, gl_b, gm_w, gm_b);
    norm_kernel<<<dim3(Bb*Ss, 2), 128>>>();

    for (int t = 0; t < NCH; t++) {
        step_gemm<0,0><<<dim3(Hh/64, Mm/64), thr>>>(t);      // pre1, a1
        step_gemm<0,1><<<dim3(Dd/64, Mm/64), thr>>>(t);      // pred -> db2
        step_gemm<1,2><<<dim3(Hh/64, Mm/64), thr>>>(t);      // db1 (old W2e)
        update_gemm<<<dim3(8, 16, 2), thr>>>(Wm1, Wm2, t);   // g1+g2 -> W1e,W2e
        step_gemm<0,5><<<dim3(Hh/64, Mm/64), thr>>>(t);      // h (new W1e)
        step_gemm<0,6><<<dim3(Dd/64, Mm/64), thr>>>(t);      // y (new W2e)
    }

    final_kernel<<<dim3(Dd/64, (Bb*Ss)/64), thr>>>(Wout, out);
}